// round 15
// baseline (speedup 1.0000x reference)
#include <cuda_runtime.h>
#include <cuda_bf16.h>
#include <math.h>
#include <stdint.h>

// Problem constants: B=4, N=1024, C=512, H=8, HD=64, SCALE=0.125
// qkv bf16 hi/lo layout: [4096 rows = b*1024+seq][2048 cols = which*512 + h*64 + d]

__device__ __nv_bfloat16 g_q1h[4096 * 2048];
__device__ __nv_bfloat16 g_q1l[4096 * 2048];
__device__ __nv_bfloat16 g_q2h[4096 * 2048];
__device__ __nv_bfloat16 g_q2l[4096 * 2048];
__device__ __nv_bfloat16 g_preh[4 * 4096 * 512];
__device__ __nv_bfloat16 g_prel[4 * 4096 * 512];
#define CV_X   0
#define CV_Y   2097152
#define CV_WQ1 4194304
#define CV_WQ2 5242880
#define CV_W0  6291456
#define CV_TOT 7340032
__device__ __nv_bfloat16 g_cvh[CV_TOT];
__device__ __nv_bfloat16 g_cvl[CV_TOT];
__device__ float g_gram[128 * 4096];   // 128 matrices of 64x64 fp32
__device__ float g_dsum[64];           // per-pair sum of diag^2
__device__ float g_part_lc[4096];

// ===========================================================================
// mma.sync machinery
// ===========================================================================
__device__ __forceinline__ uint32_t smem_u32(const void* p) {
    uint32_t a;
    asm("{ .reg .u64 t; cvta.to.shared.u64 t, %1; cvt.u32.u64 %0, t; }"
        : "=r"(a) : "l"(p));
    return a;
}
__device__ __forceinline__ void ldsm4(uint32_t* r, uint32_t addr) {
    asm volatile("ldmatrix.sync.aligned.m8n8.x4.shared.b16 {%0,%1,%2,%3}, [%4];"
                 : "=r"(r[0]), "=r"(r[1]), "=r"(r[2]), "=r"(r[3]) : "r"(addr));
}
__device__ __forceinline__ void ldsm4t(uint32_t* r, uint32_t addr) {
    asm volatile("ldmatrix.sync.aligned.m8n8.x4.trans.shared.b16 {%0,%1,%2,%3}, [%4];"
                 : "=r"(r[0]), "=r"(r[1]), "=r"(r[2]), "=r"(r[3]) : "r"(addr));
}
__device__ __forceinline__ void mma16816(float* c, const uint32_t* a,
                                         uint32_t b0, uint32_t b1) {
    asm volatile(
        "mma.sync.aligned.m16n8k16.row.col.f32.bf16.bf16.f32 "
        "{%0,%1,%2,%3}, {%4,%5,%6,%7}, {%8,%9}, {%0,%1,%2,%3};"
        : "+f"(c[0]), "+f"(c[1]), "+f"(c[2]), "+f"(c[3])
        : "r"(a[0]), "r"(a[1]), "r"(a[2]), "r"(a[3]), "r"(b0), "r"(b1));
}
__device__ __forceinline__ void cp_async16(uint32_t dst, const void* src) {
    asm volatile("cp.async.cg.shared.global [%0], [%1], 16;"
                 :: "r"(dst), "l"(src));
}
__device__ __forceinline__ void cp_commit() {
    asm volatile("cp.async.commit_group;");
}
template <int N>
__device__ __forceinline__ void cp_wait() {
    asm volatile("cp.async.wait_group %0;" :: "n"(N));
}

// ===========================================================================
// fp32 -> bf16 hi/lo conversion pass
// ===========================================================================
struct CvtArgs { const float* src[8]; };
__global__ void __launch_bounds__(256) convert_kernel(
    CvtArgs A, __nv_bfloat16* __restrict__ ch, __nv_bfloat16* __restrict__ cl)
{
    const long long off[9] = {0, 2097152, 4194304, 5242880, 6291456,
                              6553600, 6815744, 7077888, 7340032};
    long long e = ((long long)blockIdx.x * 256 + threadIdx.x) * 4;
    if (e >= CV_TOT) return;
    int r = 0;
#pragma unroll
    for (int k = 1; k < 8; k++) if (e >= off[k]) r = k;
    float4 v = *(const float4*)(A.src[r] + (e - off[r]));
    __nv_bfloat162 h0 = __floats2bfloat162_rn(v.x, v.y);
    __nv_bfloat162 h1 = __floats2bfloat162_rn(v.z, v.w);
    __nv_bfloat162 l0 = __floats2bfloat162_rn(v.x - __bfloat162float(h0.x),
                                              v.y - __bfloat162float(h0.y));
    __nv_bfloat162 l1 = __floats2bfloat162_rn(v.z - __bfloat162float(h1.x),
                                              v.w - __bfloat162float(h1.y));
    uint2 hv, lv;
    hv.x = *(uint32_t*)&h0; hv.y = *(uint32_t*)&h1;
    lv.x = *(uint32_t*)&l0; lv.y = *(uint32_t*)&l1;
    *(uint2*)(ch + e) = hv;
    *(uint2*)(cl + e) = lv;
}

// ---------------------------------------------------------------------------
// bf16-input GEMM machinery — single barrier per chunk
// ---------------------------------------------------------------------------
#define T_STRIDE_B 80
#define T_BYTES    10240
#define BUF_BYTES  40960
#define GEMM_SMEM  (2 * BUF_BYTES)

__device__ __forceinline__ void b16_load_chunk(
    uint32_t stage, const __nv_bfloat16* Ah, const __nv_bfloat16* Al,
    const __nv_bfloat16* Bh, const __nv_bfloat16* Bl, int ch, int tid)
{
#pragma unroll
    for (int l = 0; l < 8; l++) {
        int idx = tid + l * 256;
        int tile = idx >> 9, r = (idx >> 2) & 127, s = idx & 3;
        const __nv_bfloat16* src =
            (tile == 0) ? Ah : (tile == 1) ? Al : (tile == 2) ? Bh : Bl;
        cp_async16(stage + tile * T_BYTES + r * T_STRIDE_B + s * 16,
                   src + (size_t)r * 512 + ch * 32 + s * 8);
    }
}

__device__ __forceinline__ void compute_chunk(float acc[4][4][4], uint32_t sbuf,
                                              int lane, int warp_m, int warp_n) {
    const uint32_t aBase = sbuf;
    const uint32_t bBase = sbuf + 2 * T_BYTES;
#pragma unroll
    for (int kk = 0; kk < 2; kk++) {
        uint32_t Ah[4][4], Al[4][4], Bh[2][4], Bl[2][4];
#pragma unroll
        for (int mt = 0; mt < 4; mt++) {
            int row = warp_m * 64 + mt * 16 + (lane & 15);
            uint32_t addr = aBase + row * T_STRIDE_B + kk * 32 + ((lane >> 4) << 4);
            ldsm4(Ah[mt], addr);
            ldsm4(Al[mt], addr + T_BYTES);
        }
#pragma unroll
        for (int nt2 = 0; nt2 < 2; nt2++) {
            int q = lane >> 3;
            int rown = warp_n * 32 + nt2 * 16 + ((q >> 1) << 3) + (lane & 7);
            uint32_t addr = bBase + rown * T_STRIDE_B + kk * 32 + ((q & 1) << 4);
            ldsm4(Bh[nt2], addr);
            ldsm4(Bl[nt2], addr + T_BYTES);
        }
#pragma unroll
        for (int mt = 0; mt < 4; mt++)
#pragma unroll
            for (int nt = 0; nt < 4; nt++) {
                uint32_t bh0 = Bh[nt >> 1][(nt & 1) * 2];
                uint32_t bh1 = Bh[nt >> 1][(nt & 1) * 2 + 1];
                uint32_t bl0 = Bl[nt >> 1][(nt & 1) * 2];
                uint32_t bl1 = Bl[nt >> 1][(nt & 1) * 2 + 1];
                mma16816(acc[mt][nt], Ah[mt], bh0, bh1);
                mma16816(acc[mt][nt], Ah[mt], bl0, bl1);
                mma16816(acc[mt][nt], Al[mt], bh0, bh1);
            }
    }
}

__device__ __forceinline__ void b16_mainloop(
    float acc[4][4][4], const __nv_bfloat16* Ah, const __nv_bfloat16* Al,
    const __nv_bfloat16* Bh, const __nv_bfloat16* Bl,
    uint32_t sb, int tid, int lane, int warp_m, int warp_n)
{
    b16_load_chunk(sb, Ah, Al, Bh, Bl, 0, tid);
    cp_commit();
    for (int ch = 0; ch < 16; ch++) {
        cp_wait<0>();
        __syncthreads();
        if (ch + 1 < 16) {
            b16_load_chunk(sb + ((ch + 1) & 1) * BUF_BYTES, Ah, Al, Bh, Bl, ch + 1, tid);
            cp_commit();
        }
        compute_chunk(acc, sb + (ch & 1) * BUF_BYTES, lane, warp_m, warp_n);
    }
}

// ===========================================================================
// QKV projections (both in one launch): bf16 hi/lo in -> bf16 hi/lo out.
// ===========================================================================
struct QkvArgs {
    const __nv_bfloat16 *Ah[2], *Al[2], *Bh[2], *Bl[2];
    __nv_bfloat16 *Oh[2], *Ol[2];
};
__global__ void __launch_bounds__(256) hm_gemm_qkv(QkvArgs P)
{
    extern __shared__ char sm[];
    const uint32_t sb = smem_u32(sm);
    const int tid = threadIdx.x, lane = tid & 31, wid = tid >> 5;
    const int warp_m = wid >> 2, warp_n = wid & 3;
    const int Nn = 2048;
    const int z = blockIdx.z;

    const __nv_bfloat16* Ah = P.Ah[z] + (size_t)(blockIdx.y * 128) * 512;
    const __nv_bfloat16* Al = P.Al[z] + (size_t)(blockIdx.y * 128) * 512;
    const __nv_bfloat16* Bh = P.Bh[z] + (size_t)(blockIdx.x * 128) * 512;
    const __nv_bfloat16* Bl = P.Bl[z] + (size_t)(blockIdx.x * 128) * 512;
    __nv_bfloat16* Oh = P.Oh[z];
    __nv_bfloat16* Ol = P.Ol[z];

    float acc[4][4][4];
#pragma unroll
    for (int i = 0; i < 4; i++)
#pragma unroll
        for (int j = 0; j < 4; j++)
#pragma unroll
            for (int e = 0; e < 4; e++) acc[i][j][e] = 0.f;

    b16_mainloop(acc, Ah, Al, Bh, Bl, sb, tid, lane, warp_m, warp_n);

#pragma unroll
    for (int mt = 0; mt < 4; mt++)
#pragma unroll
        for (int nt = 0; nt < 4; nt++) {
            int row = blockIdx.y * 128 + warp_m * 64 + mt * 16 + (lane >> 2);
            int col = blockIdx.x * 128 + warp_n * 32 + nt * 8 + ((lane & 3) << 1);
#pragma unroll
            for (int half = 0; half < 2; half++) {
                float v0 = acc[mt][nt][half * 2], v1 = acc[mt][nt][half * 2 + 1];
                int r = row + half * 8;
                __nv_bfloat162 h = __floats2bfloat162_rn(v0, v1);
                __nv_bfloat162 l = __floats2bfloat162_rn(v0 - __bfloat162float(h.x),
                                                         v1 - __bfloat162float(h.y));
                *(uint32_t*)(Oh + (size_t)r * Nn + col) = *(uint32_t*)&h;
                *(uint32_t*)(Ol + (size_t)r * Nn + col) = *(uint32_t*)&l;
            }
        }
}

// ===========================================================================
// Batched output projections
// ===========================================================================
struct ProjArgs {
    const __nv_bfloat16 *Ah[4], *Al[4], *Bh[4], *Bl[4];
    const float* bias[4];
    float* C[4];
};
__global__ void __launch_bounds__(256) hm_proj(ProjArgs P)
{
    extern __shared__ char sm[];
    const uint32_t sb = smem_u32(sm);
    const int tid = threadIdx.x, lane = tid & 31, wid = tid >> 5;
    const int warp_m = wid >> 2, warp_n = wid & 3;
    const int Nn = 512;
    const int z = blockIdx.z;

    const __nv_bfloat16* Ah = P.Ah[z] + (size_t)(blockIdx.y * 128) * 512;
    const __nv_bfloat16* Al = P.Al[z] + (size_t)(blockIdx.y * 128) * 512;
    const __nv_bfloat16* Bh = P.Bh[z] + (size_t)(blockIdx.x * 128) * 512;
    const __nv_bfloat16* Bl = P.Bl[z] + (size_t)(blockIdx.x * 128) * 512;
    const float* bias = P.bias[z];
    float* C = P.C[z];

    float acc[4][4][4];
#pragma unroll
    for (int i = 0; i < 4; i++)
#pragma unroll
        for (int j = 0; j < 4; j++)
#pragma unroll
            for (int e = 0; e < 4; e++) acc[i][j][e] = 0.f;

    b16_mainloop(acc, Ah, Al, Bh, Bl, sb, tid, lane, warp_m, warp_n);

#pragma unroll
    for (int mt = 0; mt < 4; mt++)
#pragma unroll
        for (int nt = 0; nt < 4; nt++) {
            int row = blockIdx.y * 128 + warp_m * 64 + mt * 16 + (lane >> 2);
            int col = blockIdx.x * 128 + warp_n * 32 + nt * 8 + ((lane & 3) << 1);
            float b0 = bias[col], b1 = bias[col + 1];
            float2 v0, v1;
            v0.x = acc[mt][nt][0] + b0; v0.y = acc[mt][nt][1] + b1;
            v1.x = acc[mt][nt][2] + b0; v1.y = acc[mt][nt][3] + b1;
            *(float2*)(C + (size_t)row * Nn + col) = v0;
            *(float2*)(C + (size_t)(row + 8) * Nn + col) = v1;
        }
}

// ===========================================================================
// Ortho via trace identity (EXACT):
//   sum_offdiag G^2 = tr(C1*C2) - sum_n g_nn^2,  C1 = Qn^T Qn, C2 = Qtn^T Qtn
// gram_kernel: grid (2, 64) — computes one 64x64 gram per (pair, which).
// diag_kernel: grid 64 — per-pair sum of diag cos^2.
// ===========================================================================
__global__ void __launch_bounds__(256) gram_kernel(
    const __nv_bfloat16* __restrict__ q1h, const __nv_bfloat16* __restrict__ q1l,
    const __nv_bfloat16* __restrict__ q2h, const __nv_bfloat16* __restrict__ q2l,
    float* __restrict__ gram)
{
    __shared__ float chunk[128][68];
    __shared__ float winv[128];

    const int tid = threadIdx.x;
    const int ti = tid >> 4, tj = tid & 15;
    const int pair = blockIdx.y;          // 0..63 ; <32 -> loss x (qkv1)
    const int which = blockIdx.x;         // 0: q, 1: qt
    const int b = (pair & 31) >> 3, h = pair & 7;
    const __nv_bfloat16* bh_ = (pair < 32) ? q1h : q2h;
    const __nv_bfloat16* bl_ = (pair < 32) ? q1l : q2l;
    const size_t base = (size_t)b * 1024 * 2048 + h * 64 + which * 1536;
    const __nv_bfloat16* ph = bh_ + base;
    const __nv_bfloat16* pl = bl_ + base;

    float acc[4][4];
#pragma unroll
    for (int i = 0; i < 4; i++)
#pragma unroll
        for (int j = 0; j < 4; j++) acc[i][j] = 0.f;

    for (int ch = 0; ch < 8; ch++) {
        const int row0 = ch * 128;
        // stage 128x64 values (hi+lo reconstruct)
#pragma unroll
        for (int l = 0; l < 16; l++) {
            int idx = tid + l * 256;
            int r = idx >> 5, cp = idx & 31;
            size_t go = (size_t)(row0 + r) * 2048 + cp * 2;
            __nv_bfloat162 hv = *(const __nv_bfloat162*)(ph + go);
            __nv_bfloat162 lv = *(const __nv_bfloat162*)(pl + go);
            chunk[r][cp * 2]     = __bfloat162float(hv.x) + __bfloat162float(lv.x);
            chunk[r][cp * 2 + 1] = __bfloat162float(hv.y) + __bfloat162float(lv.y);
        }
        __syncthreads();
        if (tid < 128) {
            float ssq = 0.f;
#pragma unroll
            for (int c = 0; c < 64; c++) { float v = chunk[tid][c]; ssq += v * v; }
            winv[tid] = 1.f / fmaxf(sqrtf(ssq), 1e-12f);
        }
        __syncthreads();
#pragma unroll
        for (int l = 0; l < 32; l++) {
            int idx = tid + l * 256;
            int r = idx >> 6, c = idx & 63;
            chunk[r][c] *= winv[r];
        }
        __syncthreads();
        // accumulate C += chunk^T chunk (4x4 block per thread)
#pragma unroll 4
        for (int n = 0; n < 128; n++) {
            float4 a = *(const float4*)&chunk[n][ti * 4];
            float4 bb = *(const float4*)&chunk[n][tj * 4];
            acc[0][0] += a.x * bb.x; acc[0][1] += a.x * bb.y;
            acc[0][2] += a.x * bb.z; acc[0][3] += a.x * bb.w;
            acc[1][0] += a.y * bb.x; acc[1][1] += a.y * bb.y;
            acc[1][2] += a.y * bb.z; acc[1][3] += a.y * bb.w;
            acc[2][0] += a.z * bb.x; acc[2][1] += a.z * bb.y;
            acc[2][2] += a.z * bb.z; acc[2][3] += a.z * bb.w;
            acc[3][0] += a.w * bb.x; acc[3][1] += a.w * bb.y;
            acc[3][2] += a.w * bb.z; acc[3][3] += a.w * bb.w;
        }
        __syncthreads();
    }

    float* out = gram + (size_t)(pair * 2 + which) * 4096;
#pragma unroll
    for (int r = 0; r < 4; r++) {
        float4 v;
        v.x = acc[r][0]; v.y = acc[r][1]; v.z = acc[r][2]; v.w = acc[r][3];
        *(float4*)(out + (ti * 4 + r) * 64 + tj * 4) = v;
    }
}

__global__ void __launch_bounds__(256) diag_kernel(
    const __nv_bfloat16* __restrict__ q1h, const __nv_bfloat16* __restrict__ q1l,
    const __nv_bfloat16* __restrict__ q2h, const __nv_bfloat16* __restrict__ q2l,
    float* __restrict__ dsum)
{
    __shared__ float sh[256];
    const int tid = threadIdx.x;
    const int pair = blockIdx.x;
    const int b = (pair & 31) >> 3, h = pair & 7;
    const __nv_bfloat16* bh_ = (pair < 32) ? q1h : q2h;
    const __nv_bfloat16* bl_ = (pair < 32) ? q1l : q2l;
    const size_t base = (size_t)b * 1024 * 2048 + h * 64;

    float dd = 0.f;
#pragma unroll
    for (int l = 0; l < 4; l++) {
        int r = tid + l * 256;
        const __nv_bfloat16* ah = bh_ + base + (size_t)r * 2048;
        const __nv_bfloat16* al = bl_ + base + (size_t)r * 2048;
        const __nv_bfloat16* bhp = ah + 1536;
        const __nv_bfloat16* blp = al + 1536;
        float na = 0.f, nb = 0.f, d = 0.f;
#pragma unroll
        for (int c = 0; c < 64; c += 2) {
            __nv_bfloat162 avh = *(const __nv_bfloat162*)(ah + c);
            __nv_bfloat162 avl = *(const __nv_bfloat162*)(al + c);
            __nv_bfloat162 bvh = *(const __nv_bfloat162*)(bhp + c);
            __nv_bfloat162 bvl = *(const __nv_bfloat162*)(blp + c);
            float a0 = __bfloat162float(avh.x) + __bfloat162float(avl.x);
            float a1 = __bfloat162float(avh.y) + __bfloat162float(avl.y);
            float b0 = __bfloat162float(bvh.x) + __bfloat162float(bvl.x);
            float b1 = __bfloat162float(bvh.y) + __bfloat162float(bvl.y);
            na += a0 * a0 + a1 * a1;
            nb += b0 * b0 + b1 * b1;
            d  += a0 * b0 + a1 * b1;
        }
        float inva = 1.f / fmaxf(sqrtf(na), 1e-12f);
        float invb = 1.f / fmaxf(sqrtf(nb), 1e-12f);
        float g = d * inva * invb;
        dd += g * g;
    }
    sh[tid] = dd;
    __syncthreads();
    for (int st = 128; st > 0; st >>= 1) {
        if (tid < st) sh[tid] += sh[tid + st];
        __syncthreads();
    }
    if (tid == 0) dsum[pair] = sh[0];
}

// ===========================================================================
// HMMA flash attention: 3-stage cp.async KV ring, one barrier per iteration.
// No online softmax (bounded scores; shift-invariance).
// ===========================================================================
struct AttnArgs {
    const __nv_bfloat16* qh[4]; const __nv_bfloat16* ql[4];
    const __nv_bfloat16* kh[4]; const __nv_bfloat16* kl[4];
    const __nv_bfloat16* vh[4]; const __nv_bfloat16* vl[4];
    __nv_bfloat16* oh[4]; __nv_bfloat16* ol[4];
};
#define AQ_TILE 18432            // 128*144
#define AKV_TILE 4608            // 32*144
#define AKV_STAGE (4 * AKV_TILE) // 18432
#define ATTN_SMEM (2 * AQ_TILE + 3 * AKV_STAGE)   // 92160

__global__ void __launch_bounds__(256) attn_hmma(AttnArgs P)
{
    extern __shared__ char sm[];
    const uint32_t sb = smem_u32(sm);
    const int tid = threadIdx.x, lane = tid & 31, w = tid >> 5;

    const int z = blockIdx.z;
    const int bh = blockIdx.y;
    const int qt = blockIdx.x;
    const int b = bh >> 3, h = bh & 7;
    const size_t hoff = (size_t)b * 1024 * 2048 + h * 64;

    const __nv_bfloat16* qh_g = P.qh[z] + hoff;
    const __nv_bfloat16* ql_g = P.ql[z] + hoff;
    const __nv_bfloat16* kh_g = P.kh[z] + hoff;
    const __nv_bfloat16* kl_g = P.kl[z] + hoff;
    const __nv_bfloat16* vh_g = P.vh[z] + hoff;
    const __nv_bfloat16* vl_g = P.vl[z] + hoff;
    const size_t obase = (size_t)(b * 1024 + qt * 128) * 512 + h * 64;
    __nv_bfloat16* oh_g = P.oh[z] + obase;
    __nv_bfloat16* ol_g = P.ol[z] + obase;

    const uint32_t sQ = sb;
    const uint32_t sKV = sb + 2 * AQ_TILE;

    const int kr = tid >> 3, kseg = tid & 7;
    const uint32_t kso = kr * 144 + kseg * 16;
    const size_t kgo_base = (size_t)kr * 2048 + kseg * 8;

#pragma unroll
    for (int l = 0; l < 8; l++) {
        int idx = tid + l * 256;
        int buf = idx >> 10, r = (idx >> 3) & 127, s = idx & 7;
        const __nv_bfloat16* src = buf ? ql_g : qh_g;
        cp_async16(sQ + buf * AQ_TILE + r * 144 + s * 16,
                   src + (size_t)(qt * 128 + r) * 2048 + s * 8);
    }
    cp_commit();
#pragma unroll
    for (int t0 = 0; t0 < 2; t0++) {
        uint32_t st = sKV + t0 * AKV_STAGE;
        size_t go = kgo_base + (size_t)t0 * 32 * 2048;
        cp_async16(st + kso,                go + kh_g);
        cp_async16(st + AKV_TILE + kso,     go + kl_g);
        cp_async16(st + 2 * AKV_TILE + kso, go + vh_g);
        cp_async16(st + 3 * AKV_TILE + kso, go + vl_g);
        cp_commit();
    }

    cp_wait<2>();   // Q ready
    __syncthreads();
    uint32_t Qh[4][4], Ql[4][4];
#pragma unroll
    for (int ks = 0; ks < 4; ks++) {
        uint32_t addr = sQ + (w * 16 + (lane & 15)) * 144 + ks * 32 + ((lane >> 4) << 4);
        ldsm4(Qh[ks], addr);
        ldsm4(Ql[ks], addr + AQ_TILE);
    }

    float oacc[8][4];
#pragma unroll
    for (int f = 0; f < 8; f++)
#pragma unroll
        for (int e = 0; e < 4; e++) oacc[f][e] = 0.f;
    float l0 = 0.f, l1 = 0.f;

    for (int t = 0; t < 32; t++) {
        if (t == 31) cp_wait<0>(); else cp_wait<1>();
        __syncthreads();

        if (t + 2 < 32) {
            uint32_t st = sKV + ((t + 2) % 3) * AKV_STAGE;
            size_t go = kgo_base + (size_t)(t + 2) * 32 * 2048;
            cp_async16(st + kso,                go + kh_g);
            cp_async16(st + AKV_TILE + kso,     go + kl_g);
            cp_async16(st + 2 * AKV_TILE + kso, go + vh_g);
            cp_async16(st + 3 * AKV_TILE + kso, go + vl_g);
            cp_commit();
        }
        const uint32_t sK = sKV + (t % 3) * AKV_STAGE;

        float sacc[4][4];
#pragma unroll
        for (int nf = 0; nf < 4; nf++)
#pragma unroll
            for (int e = 0; e < 4; e++) sacc[nf][e] = 0.f;
#pragma unroll
        for (int ks = 0; ks < 4; ks++) {
            uint32_t Kh[2][4], Kl[2][4];
#pragma unroll
            for (int np = 0; np < 2; np++) {
                int q3 = lane >> 3;
                int rown = np * 16 + ((q3 >> 1) << 3) + (lane & 7);
                uint32_t addr = sK + rown * 144 + ks * 32 + ((q3 & 1) << 4);
                ldsm4(Kh[np], addr);
                ldsm4(Kl[np], addr + AKV_TILE);
            }
#pragma unroll
            for (int nf = 0; nf < 4; nf++) {
                uint32_t bh0 = Kh[nf >> 1][(nf & 1) * 2];
                uint32_t bh1 = Kh[nf >> 1][(nf & 1) * 2 + 1];
                uint32_t bl0 = Kl[nf >> 1][(nf & 1) * 2];
                uint32_t bl1 = Kl[nf >> 1][(nf & 1) * 2 + 1];
                mma16816(sacc[nf], Qh[ks], bh0, bh1);
                mma16816(sacc[nf], Qh[ks], bl0, bl1);
                mma16816(sacc[nf], Ql[ks], bh0, bh1);
            }
        }

        float p[4][4];
#pragma unroll
        for (int nf = 0; nf < 4; nf++) {
            p[nf][0] = __expf(sacc[nf][0] * 0.125f);
            p[nf][1] = __expf(sacc[nf][1] * 0.125f);
            p[nf][2] = __expf(sacc[nf][2] * 0.125f);
            p[nf][3] = __expf(sacc[nf][3] * 0.125f);
            l0 += p[nf][0] + p[nf][1];
            l1 += p[nf][2] + p[nf][3];
        }

        uint32_t Ph[2][4], Pl[2][4];
#pragma unroll
        for (int ks2 = 0; ks2 < 2; ks2++) {
#pragma unroll
            for (int j = 0; j < 2; j++) {
                int nf = 2 * ks2 + j;
#pragma unroll
                for (int hp = 0; hp < 2; hp++) {
                    float v0 = p[nf][hp * 2], v1 = p[nf][hp * 2 + 1];
                    __nv_bfloat162 hh = __floats2bfloat162_rn(v0, v1);
                    __nv_bfloat162 ll = __floats2bfloat162_rn(
                        v0 - __bfloat162float(hh.x), v1 - __bfloat162float(hh.y));
                    Ph[ks2][j * 2 + hp] = *(uint32_t*)&hh;
                    Pl[ks2][j * 2 + hp] = *(uint32_t*)&ll;
                }
            }
        }

#pragma unroll
        for (int ks2 = 0; ks2 < 2; ks2++) {
#pragma unroll
            for (int np = 0; np < 4; np++) {
                int rowv = ks2 * 16 + (((lane >> 3) & 1) << 3) + (lane & 7);
                int colv = np * 16 + ((lane >> 4) << 3);
                uint32_t addr = sK + 2 * AKV_TILE + rowv * 144 + colv * 2;
                uint32_t Vh[4], Vl[4];
                ldsm4t(Vh, addr);
                ldsm4t(Vl, addr + AKV_TILE);
                mma16816(oacc[2 * np],     Ph[ks2], Vh[0], Vh[1]);
                mma16816(oacc[2 * np],     Ph[ks2], Vl[0], Vl[1]);
                mma16816(oacc[2 * np],     Pl[ks2], Vh[0], Vh[1]);
                mma16816(oacc[2 * np + 1], Ph[ks2], Vh[2], Vh[3]);
                mma16816(oacc[2 * np + 1], Ph[ks2], Vl[2], Vl[3]);
                mma16816(oacc[2 * np + 1], Pl[ks2], Vh[2], Vh[3]);
            }
        }
    }

    l0 += __shfl_xor_sync(0xFFFFFFFFu, l0, 1);
    l0 += __shfl_xor_sync(0xFFFFFFFFu, l0, 2);
    l1 += __shfl_xor_sync(0xFFFFFFFFu, l1, 1);
    l1 += __shfl_xor_sync(0xFFFFFFFFu, l1, 2);
    float inv0 = 1.f / l0, inv1 = 1.f / l1;
    int r = w * 16 + (lane >> 2);
#pragma unroll
    for (int f = 0; f < 8; f++) {
        int c = f * 8 + ((lane & 3) << 1);
        {
            float v0 = oacc[f][0] * inv0, v1 = oacc[f][1] * inv0;
            __nv_bfloat162 hh = __floats2bfloat162_rn(v0, v1);
            __nv_bfloat162 ll = __floats2bfloat162_rn(v0 - __bfloat162float(hh.x),
                                                      v1 - __bfloat162float(hh.y));
            *(uint32_t*)(oh_g + (size_t)r * 512 + c) = *(uint32_t*)&hh;
            *(uint32_t*)(ol_g + (size_t)r * 512 + c) = *(uint32_t*)&ll;
        }
        {
            float v0 = oacc[f][2] * inv1, v1 = oacc[f][3] * inv1;
            __nv_bfloat162 hh = __floats2bfloat162_rn(v0, v1);
            __nv_bfloat162 ll = __floats2bfloat162_rn(v0 - __bfloat162float(hh.x),
                                                      v1 - __bfloat162float(hh.y));
            *(uint32_t*)(oh_g + (size_t)(r + 8) * 512 + c) = *(uint32_t*)&hh;
            *(uint32_t*)(ol_g + (size_t)(r + 8) * 512 + c) = *(uint32_t*)&ll;
        }
    }
}

// ---------------------------------------------------------------------------
// lc partials
// ---------------------------------------------------------------------------
__global__ void __launch_bounds__(128) lc_kernel(
    const float* __restrict__ xc, const float* __restrict__ yc,
    float* __restrict__ part)
{
    const int r = blockIdx.x;
    const float* xr = xc + (size_t)r * 512;
    const float* yr = yc + (size_t)r * 512;
    __shared__ float sxx[128], syy[128], sxy[128];
    const int tid = threadIdx.x;
    float xx = 0.f, yy = 0.f, xy = 0.f;
    for (int i = tid; i < 512; i += 128) {
        float xv = xr[i], yv = yr[i];
        xx += xv * xv; yy += yv * yv; xy += xv * yv;
    }
    sxx[tid] = xx; syy[tid] = yy; sxy[tid] = xy;
    __syncthreads();
    for (int st = 64; st > 0; st >>= 1) {
        if (tid < st) {
            sxx[tid] += sxx[tid + st];
            syy[tid] += syy[tid + st];
            sxy[tid] += sxy[tid + st];
        }
        __syncthreads();
    }
    if (tid == 0) {
        float nx = fmaxf(sqrtf(sxx[0]), 1e-12f);
        float ny = fmaxf(sqrtf(syy[0]), 1e-12f);
        part[r] = 1.f - sxy[0] / (nx * ny);
    }
}

// ---------------------------------------------------------------------------
// Deterministic final reductions: lorth via tr(C1*C2) - diag, then lc
// ---------------------------------------------------------------------------
__global__ void __launch_bounds__(256) finalize_kernel(
    const float* __restrict__ gram, const float* __restrict__ dsum,
    const float* __restrict__ plc, float* __restrict__ outs)
{
    __shared__ float sh[256];
    const int tid = threadIdx.x;

#pragma unroll
    for (int loss = 0; loss < 2; loss++) {
        float s = 0.f;
        const float* gb = gram + (size_t)loss * 64 * 4096;
        for (int i = tid; i < 32 * 4096; i += 256) {
            int p = i >> 12, off = i & 4095;
            s += gb[(size_t)(p * 2) * 4096 + off] * gb[(size_t)(p * 2 + 1) * 4096 + off];
        }
        sh[tid] = s; __syncthreads();
        for (int st = 128; st > 0; st >>= 1) {
            if (tid < st) sh[tid] += sh[tid + st];
            __syncthreads();
        }
        if (tid == 0) {
            float sd = 0.f;
            for (int p = 0; p < 32; p++) sd += dsum[loss * 32 + p];
            outs[loss] = (sh[0] - sd) * (1.f / 4194304.f);
        }
        __syncthreads();
    }

    float s = 0.f;
    for (int i = tid; i < 4096; i += 256) s += plc[i];
    sh[tid] = s; __syncthreads();
    for (int st = 128; st > 0; st >>= 1) { if (tid < st) sh[tid] += sh[tid + st]; __syncthreads(); }
    if (tid == 0) outs[2] = sh[0] * (1.f / 4096.f);
}

// ---------------------------------------------------------------------------
extern "C" void kernel_launch(void* const* d_in, const int* in_sizes, int n_in,
                              void* d_out, int out_size)
{
    (void)in_sizes; (void)n_in;
    const float* x   = (const float*)d_in[0];
    const float* y   = (const float*)d_in[1];
    const float* Wq1 = (const float*)d_in[2];
    const float* Wq2 = (const float*)d_in[3];
    const float* bb[4] = {(const float*)d_in[5], (const float*)d_in[7],
                          (const float*)d_in[9], (const float*)d_in[11]};
    float* out = (float*)d_out;

    __nv_bfloat16 *q1h, *q1l, *q2h, *q2l, *preh, *prel, *cvh, *cvl;
    float *gram, *dsum, *plc;
    cudaGetSymbolAddress((void**)&q1h, g_q1h);
    cudaGetSymbolAddress((void**)&q1l, g_q1l);
    cudaGetSymbolAddress((void**)&q2h, g_q2h);
    cudaGetSymbolAddress((void**)&q2l, g_q2l);
    cudaGetSymbolAddress((void**)&preh, g_preh);
    cudaGetSymbolAddress((void**)&prel, g_prel);
    cudaGetSymbolAddress((void**)&cvh, g_cvh);
    cudaGetSymbolAddress((void**)&cvl, g_cvl);
    cudaGetSymbolAddress((void**)&gram, g_gram);
    cudaGetSymbolAddress((void**)&dsum, g_dsum);
    cudaGetSymbolAddress((void**)&plc, g_part_lc);

    cudaFuncSetAttribute(hm_gemm_qkv, cudaFuncAttributeMaxDynamicSharedMemorySize, GEMM_SMEM);
    cudaFuncSetAttribute(hm_proj, cudaFuncAttributeMaxDynamicSharedMemorySize, GEMM_SMEM);
    cudaFuncSetAttribute(attn_hmma, cudaFuncAttributeMaxDynamicSharedMemorySize, ATTN_SMEM);

    static cudaStream_t s_side = nullptr;
    static cudaEvent_t ev_fork = nullptr, ev_join = nullptr;
    if (!s_side) {
        cudaStreamCreateWithFlags(&s_side, cudaStreamNonBlocking);
        cudaEventCreateWithFlags(&ev_fork, cudaEventDisableTiming);
        cudaEventCreateWithFlags(&ev_join, cudaEventDisableTiming);
    }

    const int chunk = (out_size - 3) / 4;  // 2097152 = 4096*512

    // 0) Convert all fp32 GEMM operands to bf16 hi/lo
    CvtArgs ca;
    ca.src[0] = x;            ca.src[1] = y;
    ca.src[2] = Wq1;          ca.src[3] = Wq2;
    ca.src[4] = (const float*)d_in[4];  ca.src[5] = (const float*)d_in[6];
    ca.src[6] = (const float*)d_in[8];  ca.src[7] = (const float*)d_in[10];
    convert_kernel<<<(CV_TOT / 4 + 255) / 256, 256>>>(ca, cvh, cvl);

    // 1) QKV projections -> bf16 hi/lo
    QkvArgs qa;
    qa.Ah[0] = cvh + CV_X;   qa.Al[0] = cvl + CV_X;
    qa.Bh[0] = cvh + CV_WQ1; qa.Bl[0] = cvl + CV_WQ1;
    qa.Oh[0] = q1h;          qa.Ol[0] = q1l;
    qa.Ah[1] = cvh + CV_Y;   qa.Al[1] = cvl + CV_Y;
    qa.Bh[1] = cvh + CV_WQ2; qa.Bl[1] = cvl + CV_WQ2;
    qa.Oh[1] = q2h;          qa.Ol[1] = q2l;
    hm_gemm_qkv<<<dim3(16, 32, 2), 256, GEMM_SMEM>>>(qa);

    cudaEventRecord(ev_fork, 0);

    // 2) Attention first (default stream) — ortho kernels backfill.
    AttnArgs aa;
    aa.qh[0] = q2h;        aa.ql[0] = q2l;
    aa.kh[0] = q1h + 512;  aa.kl[0] = q1l + 512;
    aa.vh[0] = q1h + 1024; aa.vl[0] = q1l + 1024;
    aa.oh[0] = preh;                 aa.ol[0] = prel;
    aa.qh[1] = q1h;        aa.ql[1] = q1l;
    aa.kh[1] = q2h + 512;  aa.kl[1] = q2l + 512;
    aa.vh[1] = q2h + 1024; aa.vl[1] = q2l + 1024;
    aa.oh[1] = preh + 2097152;       aa.ol[1] = prel + 2097152;
    aa.qh[2] = q1h + 1536; aa.ql[2] = q1l + 1536;
    aa.kh[2] = q1h + 512;  aa.kl[2] = q1l + 512;
    aa.vh[2] = q1h + 1024; aa.vl[2] = q1l + 1024;
    aa.oh[2] = preh + 2 * 2097152;   aa.ol[2] = prel + 2 * 2097152;
    aa.qh[3] = q2h + 1536; aa.ql[3] = q2l + 1536;
    aa.kh[3] = q2h + 512;  aa.kl[3] = q2l + 512;
    aa.vh[3] = q2h + 1024; aa.vl[3] = q2l + 1024;
    aa.oh[3] = preh + 3 * 2097152;   aa.ol[3] = prel + 3 * 2097152;
    attn_hmma<<<dim3(8, 32, 4), 256, ATTN_SMEM>>>(aa);

    // 3) Ortho (trace identity) on side stream, concurrent with attention.
    cudaStreamWaitEvent(s_side, ev_fork, 0);
    gram_kernel<<<dim3(2, 64), 256, 0, s_side>>>(q1h, q1l, q2h, q2l, gram);
    diag_kernel<<<64, 256, 0, s_side>>>(q1h, q1l, q2h, q2l, dsum);
    cudaEventRecord(ev_join, s_side);

    // 4) Output projections -> d_out
    ProjArgs pa;
    const int woff[4] = {CV_W0, CV_W0 + 262144, CV_W0 + 524288, CV_W0 + 786432};
    for (int i = 0; i < 4; i++) {
        pa.Ah[i] = preh + (size_t)i * 2097152;
        pa.Al[i] = prel + (size_t)i * 2097152;
        pa.Bh[i] = cvh + woff[i];
        pa.Bl[i] = cvl + woff[i];
        pa.bias[i] = bb[i];
        pa.C[i] = out + (size_t)i * chunk;
    }
    hm_proj<<<dim3(4, 32, 4), 256, GEMM_SMEM>>>(pa);

    // 5) lc on post-projection xc, yc
    lc_kernel<<<4096, 128>>>(out, out + chunk, plc);

    cudaStreamWaitEvent(0, ev_join, 0);

    // 6) scalars: lorthx, lorthy, lc
    finalize_kernel<<<1, 256>>>(gram, dsum, plc, out + (size_t)out_size - 3);
}

// round 16
// speedup vs baseline: 2.4319x; 2.4319x over previous
#include <cuda_runtime.h>
#include <cuda_bf16.h>
#include <math.h>
#include <stdint.h>

// Problem constants: B=4, N=1024, C=512, H=8, HD=64, SCALE=0.125
// qkv bf16 hi/lo layout: [4096 rows = b*1024+seq][2048 cols = which*512 + h*64 + d]

__device__ __nv_bfloat16 g_q1h[4096 * 2048];
__device__ __nv_bfloat16 g_q1l[4096 * 2048];
__device__ __nv_bfloat16 g_q2h[4096 * 2048];
__device__ __nv_bfloat16 g_q2l[4096 * 2048];
__device__ __nv_bfloat16 g_preh[4 * 4096 * 512];
__device__ __nv_bfloat16 g_prel[4 * 4096 * 512];
#define CV_X   0
#define CV_Y   2097152
#define CV_WQ1 4194304
#define CV_WQ2 5242880
#define CV_W0  6291456
#define CV_TOT 7340032
__device__ __nv_bfloat16 g_cvh[CV_TOT];
__device__ __nv_bfloat16 g_cvl[CV_TOT];
__device__ float g_part_orth[16384];
__device__ float g_part_lc[4096];

// ===========================================================================
// mma.sync machinery
// ===========================================================================
__device__ __forceinline__ uint32_t smem_u32(const void* p) {
    uint32_t a;
    asm("{ .reg .u64 t; cvta.to.shared.u64 t, %1; cvt.u32.u64 %0, t; }"
        : "=r"(a) : "l"(p));
    return a;
}
__device__ __forceinline__ void ldsm4(uint32_t* r, uint32_t addr) {
    asm volatile("ldmatrix.sync.aligned.m8n8.x4.shared.b16 {%0,%1,%2,%3}, [%4];"
                 : "=r"(r[0]), "=r"(r[1]), "=r"(r[2]), "=r"(r[3]) : "r"(addr));
}
__device__ __forceinline__ void ldsm4t(uint32_t* r, uint32_t addr) {
    asm volatile("ldmatrix.sync.aligned.m8n8.x4.trans.shared.b16 {%0,%1,%2,%3}, [%4];"
                 : "=r"(r[0]), "=r"(r[1]), "=r"(r[2]), "=r"(r[3]) : "r"(addr));
}
__device__ __forceinline__ void mma16816(float* c, const uint32_t* a,
                                         uint32_t b0, uint32_t b1) {
    asm volatile(
        "mma.sync.aligned.m16n8k16.row.col.f32.bf16.bf16.f32 "
        "{%0,%1,%2,%3}, {%4,%5,%6,%7}, {%8,%9}, {%0,%1,%2,%3};"
        : "+f"(c[0]), "+f"(c[1]), "+f"(c[2]), "+f"(c[3])
        : "r"(a[0]), "r"(a[1]), "r"(a[2]), "r"(a[3]), "r"(b0), "r"(b1));
}
__device__ __forceinline__ void cp_async16(uint32_t dst, const void* src) {
    asm volatile("cp.async.cg.shared.global [%0], [%1], 16;"
                 :: "r"(dst), "l"(src));
}
__device__ __forceinline__ void cp_commit() {
    asm volatile("cp.async.commit_group;");
}
template <int N>
__device__ __forceinline__ void cp_wait() {
    asm volatile("cp.async.wait_group %0;" :: "n"(N));
}

// ===========================================================================
// fp32 -> bf16 hi/lo conversion pass
// ===========================================================================
struct CvtArgs { const float* src[8]; };
__global__ void __launch_bounds__(256) convert_kernel(
    CvtArgs A, __nv_bfloat16* __restrict__ ch, __nv_bfloat16* __restrict__ cl)
{
    const long long off[9] = {0, 2097152, 4194304, 5242880, 6291456,
                              6553600, 6815744, 7077888, 7340032};
    long long e = ((long long)blockIdx.x * 256 + threadIdx.x) * 4;
    if (e >= CV_TOT) return;
    int r = 0;
#pragma unroll
    for (int k = 1; k < 8; k++) if (e >= off[k]) r = k;
    float4 v = *(const float4*)(A.src[r] + (e - off[r]));
    __nv_bfloat162 h0 = __floats2bfloat162_rn(v.x, v.y);
    __nv_bfloat162 h1 = __floats2bfloat162_rn(v.z, v.w);
    __nv_bfloat162 l0 = __floats2bfloat162_rn(v.x - __bfloat162float(h0.x),
                                              v.y - __bfloat162float(h0.y));
    __nv_bfloat162 l1 = __floats2bfloat162_rn(v.z - __bfloat162float(h1.x),
                                              v.w - __bfloat162float(h1.y));
    uint2 hv, lv;
    hv.x = *(uint32_t*)&h0; hv.y = *(uint32_t*)&h1;
    lv.x = *(uint32_t*)&l0; lv.y = *(uint32_t*)&l1;
    *(uint2*)(ch + e) = hv;
    *(uint2*)(cl + e) = lv;
}

// ---------------------------------------------------------------------------
// bf16-input GEMM machinery — single barrier per chunk
// ---------------------------------------------------------------------------
#define T_STRIDE_B 80
#define T_BYTES    10240
#define BUF_BYTES  40960
#define GEMM_SMEM  (2 * BUF_BYTES)

__device__ __forceinline__ void b16_load_chunk(
    uint32_t stage, const __nv_bfloat16* Ah, const __nv_bfloat16* Al,
    const __nv_bfloat16* Bh, const __nv_bfloat16* Bl, int ch, int tid)
{
#pragma unroll
    for (int l = 0; l < 8; l++) {
        int idx = tid + l * 256;
        int tile = idx >> 9, r = (idx >> 2) & 127, s = idx & 3;
        const __nv_bfloat16* src =
            (tile == 0) ? Ah : (tile == 1) ? Al : (tile == 2) ? Bh : Bl;
        cp_async16(stage + tile * T_BYTES + r * T_STRIDE_B + s * 16,
                   src + (size_t)r * 512 + ch * 32 + s * 8);
    }
}

__device__ __forceinline__ void compute_chunk(float acc[4][4][4], uint32_t sbuf,
                                              int lane, int warp_m, int warp_n) {
    const uint32_t aBase = sbuf;
    const uint32_t bBase = sbuf + 2 * T_BYTES;
#pragma unroll
    for (int kk = 0; kk < 2; kk++) {
        uint32_t Ah[4][4], Al[4][4], Bh[2][4], Bl[2][4];
#pragma unroll
        for (int mt = 0; mt < 4; mt++) {
            int row = warp_m * 64 + mt * 16 + (lane & 15);
            uint32_t addr = aBase + row * T_STRIDE_B + kk * 32 + ((lane >> 4) << 4);
            ldsm4(Ah[mt], addr);
            ldsm4(Al[mt], addr + T_BYTES);
        }
#pragma unroll
        for (int nt2 = 0; nt2 < 2; nt2++) {
            int q = lane >> 3;
            int rown = warp_n * 32 + nt2 * 16 + ((q >> 1) << 3) + (lane & 7);
            uint32_t addr = bBase + rown * T_STRIDE_B + kk * 32 + ((q & 1) << 4);
            ldsm4(Bh[nt2], addr);
            ldsm4(Bl[nt2], addr + T_BYTES);
        }
#pragma unroll
        for (int mt = 0; mt < 4; mt++)
#pragma unroll
            for (int nt = 0; nt < 4; nt++) {
                uint32_t bh0 = Bh[nt >> 1][(nt & 1) * 2];
                uint32_t bh1 = Bh[nt >> 1][(nt & 1) * 2 + 1];
                uint32_t bl0 = Bl[nt >> 1][(nt & 1) * 2];
                uint32_t bl1 = Bl[nt >> 1][(nt & 1) * 2 + 1];
                mma16816(acc[mt][nt], Ah[mt], bh0, bh1);
                mma16816(acc[mt][nt], Ah[mt], bl0, bl1);
                mma16816(acc[mt][nt], Al[mt], bh0, bh1);
            }
    }
}

__device__ __forceinline__ void b16_mainloop(
    float acc[4][4][4], const __nv_bfloat16* Ah, const __nv_bfloat16* Al,
    const __nv_bfloat16* Bh, const __nv_bfloat16* Bl,
    uint32_t sb, int tid, int lane, int warp_m, int warp_n)
{
    b16_load_chunk(sb, Ah, Al, Bh, Bl, 0, tid);
    cp_commit();
    for (int ch = 0; ch < 16; ch++) {
        cp_wait<0>();
        __syncthreads();
        if (ch + 1 < 16) {
            b16_load_chunk(sb + ((ch + 1) & 1) * BUF_BYTES, Ah, Al, Bh, Bl, ch + 1, tid);
            cp_commit();
        }
        compute_chunk(acc, sb + (ch & 1) * BUF_BYTES, lane, warp_m, warp_n);
    }
}

// ===========================================================================
// QKV projections (both in one launch): bf16 hi/lo in -> bf16 hi/lo out.
// ===========================================================================
struct QkvArgs {
    const __nv_bfloat16 *Ah[2], *Al[2], *Bh[2], *Bl[2];
    __nv_bfloat16 *Oh[2], *Ol[2];
};
__global__ void __launch_bounds__(256) hm_gemm_qkv(QkvArgs P)
{
    extern __shared__ char sm[];
    const uint32_t sb = smem_u32(sm);
    const int tid = threadIdx.x, lane = tid & 31, wid = tid >> 5;
    const int warp_m = wid >> 2, warp_n = wid & 3;
    const int Nn = 2048;
    const int z = blockIdx.z;

    const __nv_bfloat16* Ah = P.Ah[z] + (size_t)(blockIdx.y * 128) * 512;
    const __nv_bfloat16* Al = P.Al[z] + (size_t)(blockIdx.y * 128) * 512;
    const __nv_bfloat16* Bh = P.Bh[z] + (size_t)(blockIdx.x * 128) * 512;
    const __nv_bfloat16* Bl = P.Bl[z] + (size_t)(blockIdx.x * 128) * 512;
    __nv_bfloat16* Oh = P.Oh[z];
    __nv_bfloat16* Ol = P.Ol[z];

    float acc[4][4][4];
#pragma unroll
    for (int i = 0; i < 4; i++)
#pragma unroll
        for (int j = 0; j < 4; j++)
#pragma unroll
            for (int e = 0; e < 4; e++) acc[i][j][e] = 0.f;

    b16_mainloop(acc, Ah, Al, Bh, Bl, sb, tid, lane, warp_m, warp_n);

#pragma unroll
    for (int mt = 0; mt < 4; mt++)
#pragma unroll
        for (int nt = 0; nt < 4; nt++) {
            int row = blockIdx.y * 128 + warp_m * 64 + mt * 16 + (lane >> 2);
            int col = blockIdx.x * 128 + warp_n * 32 + nt * 8 + ((lane & 3) << 1);
#pragma unroll
            for (int half = 0; half < 2; half++) {
                float v0 = acc[mt][nt][half * 2], v1 = acc[mt][nt][half * 2 + 1];
                int r = row + half * 8;
                __nv_bfloat162 h = __floats2bfloat162_rn(v0, v1);
                __nv_bfloat162 l = __floats2bfloat162_rn(v0 - __bfloat162float(h.x),
                                                         v1 - __bfloat162float(h.y));
                *(uint32_t*)(Oh + (size_t)r * Nn + col) = *(uint32_t*)&h;
                *(uint32_t*)(Ol + (size_t)r * Nn + col) = *(uint32_t*)&l;
            }
        }
}

// ===========================================================================
// Batched output projections
// ===========================================================================
struct ProjArgs {
    const __nv_bfloat16 *Ah[4], *Al[4], *Bh[4], *Bl[4];
    const float* bias[4];
    float* C[4];
};
__global__ void __launch_bounds__(256) hm_proj(ProjArgs P)
{
    extern __shared__ char sm[];
    const uint32_t sb = smem_u32(sm);
    const int tid = threadIdx.x, lane = tid & 31, wid = tid >> 5;
    const int warp_m = wid >> 2, warp_n = wid & 3;
    const int Nn = 512;
    const int z = blockIdx.z;

    const __nv_bfloat16* Ah = P.Ah[z] + (size_t)(blockIdx.y * 128) * 512;
    const __nv_bfloat16* Al = P.Al[z] + (size_t)(blockIdx.y * 128) * 512;
    const __nv_bfloat16* Bh = P.Bh[z] + (size_t)(blockIdx.x * 128) * 512;
    const __nv_bfloat16* Bl = P.Bl[z] + (size_t)(blockIdx.x * 128) * 512;
    const float* bias = P.bias[z];
    float* C = P.C[z];

    float acc[4][4][4];
#pragma unroll
    for (int i = 0; i < 4; i++)
#pragma unroll
        for (int j = 0; j < 4; j++)
#pragma unroll
            for (int e = 0; e < 4; e++) acc[i][j][e] = 0.f;

    b16_mainloop(acc, Ah, Al, Bh, Bl, sb, tid, lane, warp_m, warp_n);

#pragma unroll
    for (int mt = 0; mt < 4; mt++)
#pragma unroll
        for (int nt = 0; nt < 4; nt++) {
            int row = blockIdx.y * 128 + warp_m * 64 + mt * 16 + (lane >> 2);
            int col = blockIdx.x * 128 + warp_n * 32 + nt * 8 + ((lane & 3) << 1);
            float b0 = bias[col], b1 = bias[col + 1];
            float2 v0, v1;
            v0.x = acc[mt][nt][0] + b0; v0.y = acc[mt][nt][1] + b1;
            v1.x = acc[mt][nt][2] + b0; v1.y = acc[mt][nt][3] + b1;
            *(float2*)(C + (size_t)row * Nn + col) = v0;
            *(float2*)(C + (size_t)(row + 8) * Nn + col) = v1;
        }
}

// ===========================================================================
// Ortho loss: 2-term split (Ah x (Bh+Bl)). grid (8, 8, 64), 256 thr.
// ===========================================================================
#define OT_TILE 18432           // 128 * 144
#define ORTHO_SMEM (4 * OT_TILE + 1024)

__global__ void __launch_bounds__(256) hm_ortho(
    const __nv_bfloat16* __restrict__ q1h, const __nv_bfloat16* __restrict__ q1l,
    const __nv_bfloat16* __restrict__ q2h, const __nv_bfloat16* __restrict__ q2l,
    float* __restrict__ part)
{
    extern __shared__ char sm[];
    const uint32_t sb = smem_u32(sm);
    float* inva = (float*)(sm + 4 * OT_TILE);
    float* invb = (float*)(sm + 4 * OT_TILE + 512);

    const int tid = threadIdx.x, lane = tid & 31, wid = tid >> 5;
    const int warp_m = wid >> 2, warp_n = wid & 3;

    const int z = blockIdx.z;
    const int bh = z & 31;
    const int b = bh >> 3, h = bh & 7;
    const __nv_bfloat16* baseh = (z < 32) ? q1h : q2h;
    const __nv_bfloat16* basel = (z < 32) ? q1l : q2l;
    const size_t hoff = (size_t)b * 1024 * 2048 + h * 64;
    const int i0 = blockIdx.y * 128, j0 = blockIdx.x * 128;
    const __nv_bfloat16* Ah_g = baseh + hoff + (size_t)i0 * 2048;
    const __nv_bfloat16* Al_g = basel + hoff + (size_t)i0 * 2048;
    const __nv_bfloat16* Bh_g = baseh + hoff + 1536 + (size_t)j0 * 2048;
    const __nv_bfloat16* Bl_g = basel + hoff + 1536 + (size_t)j0 * 2048;

#pragma unroll
    for (int l = 0; l < 16; l++) {
        int idx = tid + l * 256;
        int tile = idx >> 10, r = (idx >> 3) & 127, s = idx & 7;
        const __nv_bfloat16* src =
            (tile == 0) ? Ah_g : (tile == 1) ? Al_g : (tile == 2) ? Bh_g : Bl_g;
        cp_async16(sb + tile * OT_TILE + r * 144 + s * 16, src + (size_t)r * 2048 + s * 8);
    }
    cp_commit();
    cp_wait<0>();
    __syncthreads();

    {
        int tile = (tid < 128) ? 0 : 2;
        int r = tid & 127;
        const __nv_bfloat16* ph = (const __nv_bfloat16*)(sm + tile * OT_TILE + r * 144);
        const __nv_bfloat16* pl = (const __nv_bfloat16*)(sm + (tile + 1) * OT_TILE + r * 144);
        float ssq = 0.f;
#pragma unroll
        for (int c = 0; c < 64; c++) {
            float v = __bfloat162float(ph[c]) + __bfloat162float(pl[c]);
            ssq += v * v;
        }
        float inv = 1.f / fmaxf(sqrtf(ssq), 1e-12f);
        if (tid < 128) inva[r] = inv;
        else           invb[r] = inv;
    }
    __syncthreads();

    float acc[4][4][4];
#pragma unroll
    for (int i = 0; i < 4; i++)
#pragma unroll
        for (int j = 0; j < 4; j++)
#pragma unroll
            for (int e = 0; e < 4; e++) acc[i][j][e] = 0.f;

#pragma unroll
    for (int ks = 0; ks < 4; ks++) {
        uint32_t Af[4][4], Bf[2][4], Blf[2][4];
#pragma unroll
        for (int mt = 0; mt < 4; mt++) {
            uint32_t addr = sb + (warp_m * 64 + mt * 16 + (lane & 15)) * 144
                          + ks * 32 + ((lane >> 4) << 4);
            ldsm4(Af[mt], addr);
        }
#pragma unroll
        for (int np = 0; np < 2; np++) {
            int q3 = lane >> 3;
            int rown = warp_n * 32 + np * 16 + ((q3 >> 1) << 3) + (lane & 7);
            uint32_t addr = sb + 2 * OT_TILE + rown * 144 + ks * 32 + ((q3 & 1) << 4);
            ldsm4(Bf[np], addr);
            ldsm4(Blf[np], addr + OT_TILE);
        }
#pragma unroll
        for (int mt = 0; mt < 4; mt++)
#pragma unroll
            for (int nt = 0; nt < 4; nt++) {
                uint32_t bh0 = Bf[nt >> 1][(nt & 1) * 2];
                uint32_t bh1 = Bf[nt >> 1][(nt & 1) * 2 + 1];
                uint32_t bl0 = Blf[nt >> 1][(nt & 1) * 2];
                uint32_t bl1 = Blf[nt >> 1][(nt & 1) * 2 + 1];
                mma16816(acc[mt][nt], Af[mt], bh0, bh1);
                mma16816(acc[mt][nt], Af[mt], bl0, bl1);
            }
    }

    float ssum = 0.f;
#pragma unroll
    for (int mt = 0; mt < 4; mt++)
#pragma unroll
        for (int nt = 0; nt < 4; nt++) {
            int r = warp_m * 64 + mt * 16 + (lane >> 2);
            int c = warp_n * 32 + nt * 8 + ((lane & 3) << 1);
            int gi0 = i0 + r, gi1 = gi0 + 8;
            int gj0 = j0 + c, gj1 = gj0 + 1;
            float ia0 = inva[r], ia1 = inva[r + 8];
            float ib0 = invb[c], ib1 = invb[c + 1];
            float g00 = acc[mt][nt][0] * ia0 * ib0;
            float g01 = acc[mt][nt][1] * ia0 * ib1;
            float g10 = acc[mt][nt][2] * ia1 * ib0;
            float g11 = acc[mt][nt][3] * ia1 * ib1;
            if (gi0 != gj0) ssum += g00 * g00;
            if (gi0 != gj1) ssum += g01 * g01;
            if (gi1 != gj0) ssum += g10 * g10;
            if (gi1 != gj1) ssum += g11 * g11;
        }

    __syncthreads();
    float* rb = (float*)sm;
    rb[tid] = ssum;
    __syncthreads();
    for (int st = 128; st > 0; st >>= 1) {
        if (tid < st) rb[tid] += rb[tid + st];
        __syncthreads();
    }
    if (tid == 0)
        part[(size_t)z * 64 + blockIdx.y * 8 + blockIdx.x] = rb[0];
}

// ===========================================================================
// HMMA flash attention: 3-stage cp.async KV ring, one barrier per iteration.
// No online softmax (bounded scores). S uses 2-term split: Qh x (Kh+Kl)
// (Ql term dropped; est. output rel err ~4e-4, under the 1e-3 gate).
// ===========================================================================
struct AttnArgs {
    const __nv_bfloat16* qh[4];
    const __nv_bfloat16* kh[4]; const __nv_bfloat16* kl[4];
    const __nv_bfloat16* vh[4]; const __nv_bfloat16* vl[4];
    __nv_bfloat16* oh[4]; __nv_bfloat16* ol[4];
};
#define AQ_TILE 18432            // 128*144
#define AKV_TILE 4608            // 32*144
#define AKV_STAGE (4 * AKV_TILE) // 18432
#define ATTN_SMEM (AQ_TILE + 3 * AKV_STAGE)   // 73728

__global__ void __launch_bounds__(256) attn_hmma(AttnArgs P)
{
    extern __shared__ char sm[];
    const uint32_t sb = smem_u32(sm);
    const int tid = threadIdx.x, lane = tid & 31, w = tid >> 5;

    const int z = blockIdx.z;
    const int bh = blockIdx.y;
    const int qt = blockIdx.x;
    const int b = bh >> 3, h = bh & 7;
    const size_t hoff = (size_t)b * 1024 * 2048 + h * 64;

    const __nv_bfloat16* qh_g = P.qh[z] + hoff;
    const __nv_bfloat16* kh_g = P.kh[z] + hoff;
    const __nv_bfloat16* kl_g = P.kl[z] + hoff;
    const __nv_bfloat16* vh_g = P.vh[z] + hoff;
    const __nv_bfloat16* vl_g = P.vl[z] + hoff;
    const size_t obase = (size_t)(b * 1024 + qt * 128) * 512 + h * 64;
    __nv_bfloat16* oh_g = P.oh[z] + obase;
    __nv_bfloat16* ol_g = P.ol[z] + obase;

    const uint32_t sQ = sb;
    const uint32_t sKV = sb + AQ_TILE;

    const int kr = tid >> 3, kseg = tid & 7;
    const uint32_t kso = kr * 144 + kseg * 16;
    const size_t kgo_base = (size_t)kr * 2048 + kseg * 8;

    // ---- Prologue: Q hi tile only, KV stage 0, KV stage 1 ----
#pragma unroll
    for (int l = 0; l < 4; l++) {
        int idx = tid + l * 256;
        int r = idx >> 3, s = idx & 7;
        cp_async16(sQ + r * 144 + s * 16,
                   qh_g + (size_t)(qt * 128 + r) * 2048 + s * 8);
    }
    cp_commit();
#pragma unroll
    for (int t0 = 0; t0 < 2; t0++) {
        uint32_t st = sKV + t0 * AKV_STAGE;
        size_t go = kgo_base + (size_t)t0 * 32 * 2048;
        cp_async16(st + kso,                go + kh_g);
        cp_async16(st + AKV_TILE + kso,     go + kl_g);
        cp_async16(st + 2 * AKV_TILE + kso, go + vh_g);
        cp_async16(st + 3 * AKV_TILE + kso, go + vl_g);
        cp_commit();
    }

    cp_wait<2>();   // Q ready
    __syncthreads();
    uint32_t Qh[4][4];
#pragma unroll
    for (int ks = 0; ks < 4; ks++) {
        uint32_t addr = sQ + (w * 16 + (lane & 15)) * 144 + ks * 32 + ((lane >> 4) << 4);
        ldsm4(Qh[ks], addr);
    }

    float oacc[8][4];
#pragma unroll
    for (int f = 0; f < 8; f++)
#pragma unroll
        for (int e = 0; e < 4; e++) oacc[f][e] = 0.f;
    float l0 = 0.f, l1 = 0.f;

    for (int t = 0; t < 32; t++) {
        if (t == 31) cp_wait<0>(); else cp_wait<1>();
        __syncthreads();

        if (t + 2 < 32) {
            uint32_t st = sKV + ((t + 2) % 3) * AKV_STAGE;
            size_t go = kgo_base + (size_t)(t + 2) * 32 * 2048;
            cp_async16(st + kso,                go + kh_g);
            cp_async16(st + AKV_TILE + kso,     go + kl_g);
            cp_async16(st + 2 * AKV_TILE + kso, go + vh_g);
            cp_async16(st + 3 * AKV_TILE + kso, go + vl_g);
            cp_commit();
        }
        const uint32_t sK = sKV + (t % 3) * AKV_STAGE;

        // ---- S = Q K^T, 2-term split (Qh x Kh + Qh x Kl) ----
        float sacc[4][4];
#pragma unroll
        for (int nf = 0; nf < 4; nf++)
#pragma unroll
            for (int e = 0; e < 4; e++) sacc[nf][e] = 0.f;
#pragma unroll
        for (int ks = 0; ks < 4; ks++) {
            uint32_t Kh[2][4], Kl[2][4];
#pragma unroll
            for (int np = 0; np < 2; np++) {
                int q3 = lane >> 3;
                int rown = np * 16 + ((q3 >> 1) << 3) + (lane & 7);
                uint32_t addr = sK + rown * 144 + ks * 32 + ((q3 & 1) << 4);
                ldsm4(Kh[np], addr);
                ldsm4(Kl[np], addr + AKV_TILE);
            }
#pragma unroll
            for (int nf = 0; nf < 4; nf++) {
                uint32_t bh0 = Kh[nf >> 1][(nf & 1) * 2];
                uint32_t bh1 = Kh[nf >> 1][(nf & 1) * 2 + 1];
                uint32_t bl0 = Kl[nf >> 1][(nf & 1) * 2];
                uint32_t bl1 = Kl[nf >> 1][(nf & 1) * 2 + 1];
                mma16816(sacc[nf], Qh[ks], bh0, bh1);
                mma16816(sacc[nf], Qh[ks], bl0, bl1);
            }
        }

        // ---- p = exp(s * SCALE); accumulate per-thread row sums ----
        float p[4][4];
#pragma unroll
        for (int nf = 0; nf < 4; nf++) {
            p[nf][0] = __expf(sacc[nf][0] * 0.125f);
            p[nf][1] = __expf(sacc[nf][1] * 0.125f);
            p[nf][2] = __expf(sacc[nf][2] * 0.125f);
            p[nf][3] = __expf(sacc[nf][3] * 0.125f);
            l0 += p[nf][0] + p[nf][1];
            l1 += p[nf][2] + p[nf][3];
        }

        // ---- P fragments (bf16 hi/lo split) ----
        uint32_t Ph[2][4], Pl[2][4];
#pragma unroll
        for (int ks2 = 0; ks2 < 2; ks2++) {
#pragma unroll
            for (int j = 0; j < 2; j++) {
                int nf = 2 * ks2 + j;
#pragma unroll
                for (int hp = 0; hp < 2; hp++) {
                    float v0 = p[nf][hp * 2], v1 = p[nf][hp * 2 + 1];
                    __nv_bfloat162 hh = __floats2bfloat162_rn(v0, v1);
                    __nv_bfloat162 ll = __floats2bfloat162_rn(
                        v0 - __bfloat162float(hh.x), v1 - __bfloat162float(hh.y));
                    Ph[ks2][j * 2 + hp] = *(uint32_t*)&hh;
                    Pl[ks2][j * 2 + hp] = *(uint32_t*)&ll;
                }
            }
        }

        // ---- O += P V, 3-term split ----
#pragma unroll
        for (int ks2 = 0; ks2 < 2; ks2++) {
#pragma unroll
            for (int np = 0; np < 4; np++) {
                int rowv = ks2 * 16 + (((lane >> 3) & 1) << 3) + (lane & 7);
                int colv = np * 16 + ((lane >> 4) << 3);
                uint32_t addr = sK + 2 * AKV_TILE + rowv * 144 + colv * 2;
                uint32_t Vh[4], Vl[4];
                ldsm4t(Vh, addr);
                ldsm4t(Vl, addr + AKV_TILE);
                mma16816(oacc[2 * np],     Ph[ks2], Vh[0], Vh[1]);
                mma16816(oacc[2 * np],     Ph[ks2], Vl[0], Vl[1]);
                mma16816(oacc[2 * np],     Pl[ks2], Vh[0], Vh[1]);
                mma16816(oacc[2 * np + 1], Ph[ks2], Vh[2], Vh[3]);
                mma16816(oacc[2 * np + 1], Ph[ks2], Vl[2], Vl[3]);
                mma16816(oacc[2 * np + 1], Pl[ks2], Vh[2], Vh[3]);
            }
        }
    }

    l0 += __shfl_xor_sync(0xFFFFFFFFu, l0, 1);
    l0 += __shfl_xor_sync(0xFFFFFFFFu, l0, 2);
    l1 += __shfl_xor_sync(0xFFFFFFFFu, l1, 1);
    l1 += __shfl_xor_sync(0xFFFFFFFFu, l1, 2);
    float inv0 = 1.f / l0, inv1 = 1.f / l1;
    int r = w * 16 + (lane >> 2);
#pragma unroll
    for (int f = 0; f < 8; f++) {
        int c = f * 8 + ((lane & 3) << 1);
        {
            float v0 = oacc[f][0] * inv0, v1 = oacc[f][1] * inv0;
            __nv_bfloat162 hh = __floats2bfloat162_rn(v0, v1);
            __nv_bfloat162 ll = __floats2bfloat162_rn(v0 - __bfloat162float(hh.x),
                                                      v1 - __bfloat162float(hh.y));
            *(uint32_t*)(oh_g + (size_t)r * 512 + c) = *(uint32_t*)&hh;
            *(uint32_t*)(ol_g + (size_t)r * 512 + c) = *(uint32_t*)&ll;
        }
        {
            float v0 = oacc[f][2] * inv1, v1 = oacc[f][3] * inv1;
            __nv_bfloat162 hh = __floats2bfloat162_rn(v0, v1);
            __nv_bfloat162 ll = __floats2bfloat162_rn(v0 - __bfloat162float(hh.x),
                                                      v1 - __bfloat162float(hh.y));
            *(uint32_t*)(oh_g + (size_t)(r + 8) * 512 + c) = *(uint32_t*)&hh;
            *(uint32_t*)(ol_g + (size_t)(r + 8) * 512 + c) = *(uint32_t*)&ll;
        }
    }
}

// ---------------------------------------------------------------------------
// lc partials
// ---------------------------------------------------------------------------
__global__ void __launch_bounds__(128) lc_kernel(
    const float* __restrict__ xc, const float* __restrict__ yc,
    float* __restrict__ part)
{
    const int r = blockIdx.x;
    const float* xr = xc + (size_t)r * 512;
    const float* yr = yc + (size_t)r * 512;
    __shared__ float sxx[128], syy[128], sxy[128];
    const int tid = threadIdx.x;
    float xx = 0.f, yy = 0.f, xy = 0.f;
    for (int i = tid; i < 512; i += 128) {
        float xv = xr[i], yv = yr[i];
        xx += xv * xv; yy += yv * yv; xy += xv * yv;
    }
    sxx[tid] = xx; syy[tid] = yy; sxy[tid] = xy;
    __syncthreads();
    for (int st = 64; st > 0; st >>= 1) {
        if (tid < st) {
            sxx[tid] += sxx[tid + st];
            syy[tid] += syy[tid + st];
            sxy[tid] += sxy[tid + st];
        }
        __syncthreads();
    }
    if (tid == 0) {
        float nx = fmaxf(sqrtf(sxx[0]), 1e-12f);
        float ny = fmaxf(sqrtf(syy[0]), 1e-12f);
        part[r] = 1.f - sxy[0] / (nx * ny);
    }
}

// ---------------------------------------------------------------------------
// Deterministic final reductions
// ---------------------------------------------------------------------------
__global__ void __launch_bounds__(256) finalize_kernel(
    const float* __restrict__ porth, const float* __restrict__ plc,
    float* __restrict__ outs)
{
    __shared__ float sh[256];
    const int tid = threadIdx.x;

    float s = 0.f;
    for (int i = tid; i < 2048; i += 256) s += porth[i];
    sh[tid] = s; __syncthreads();
    for (int st = 128; st > 0; st >>= 1) { if (tid < st) sh[tid] += sh[tid + st]; __syncthreads(); }
    if (tid == 0) outs[0] = sh[0] * (1.f / 4194304.f);
    __syncthreads();

    s = 0.f;
    for (int i = tid; i < 2048; i += 256) s += porth[2048 + i];
    sh[tid] = s; __syncthreads();
    for (int st = 128; st > 0; st >>= 1) { if (tid < st) sh[tid] += sh[tid + st]; __syncthreads(); }
    if (tid == 0) outs[1] = sh[0] * (1.f / 4194304.f);
    __syncthreads();

    s = 0.f;
    for (int i = tid; i < 4096; i += 256) s += plc[i];
    sh[tid] = s; __syncthreads();
    for (int st = 128; st > 0; st >>= 1) { if (tid < st) sh[tid] += sh[tid + st]; __syncthreads(); }
    if (tid == 0) outs[2] = sh[0] * (1.f / 4096.f);
}

// ---------------------------------------------------------------------------
extern "C" void kernel_launch(void* const* d_in, const int* in_sizes, int n_in,
                              void* d_out, int out_size)
{
    (void)in_sizes; (void)n_in;
    const float* x   = (const float*)d_in[0];
    const float* y   = (const float*)d_in[1];
    const float* Wq1 = (const float*)d_in[2];
    const float* Wq2 = (const float*)d_in[3];
    const float* bb[4] = {(const float*)d_in[5], (const float*)d_in[7],
                          (const float*)d_in[9], (const float*)d_in[11]};
    float* out = (float*)d_out;

    __nv_bfloat16 *q1h, *q1l, *q2h, *q2l, *preh, *prel, *cvh, *cvl;
    float *porth, *plc;
    cudaGetSymbolAddress((void**)&q1h, g_q1h);
    cudaGetSymbolAddress((void**)&q1l, g_q1l);
    cudaGetSymbolAddress((void**)&q2h, g_q2h);
    cudaGetSymbolAddress((void**)&q2l, g_q2l);
    cudaGetSymbolAddress((void**)&preh, g_preh);
    cudaGetSymbolAddress((void**)&prel, g_prel);
    cudaGetSymbolAddress((void**)&cvh, g_cvh);
    cudaGetSymbolAddress((void**)&cvl, g_cvl);
    cudaGetSymbolAddress((void**)&porth, g_part_orth);
    cudaGetSymbolAddress((void**)&plc, g_part_lc);

    cudaFuncSetAttribute(hm_gemm_qkv, cudaFuncAttributeMaxDynamicSharedMemorySize, GEMM_SMEM);
    cudaFuncSetAttribute(hm_proj, cudaFuncAttributeMaxDynamicSharedMemorySize, GEMM_SMEM);
    cudaFuncSetAttribute(hm_ortho, cudaFuncAttributeMaxDynamicSharedMemorySize, ORTHO_SMEM);
    cudaFuncSetAttribute(attn_hmma, cudaFuncAttributeMaxDynamicSharedMemorySize, ATTN_SMEM);

    static cudaStream_t s_side = nullptr;
    static cudaEvent_t ev_fork = nullptr, ev_join = nullptr;
    if (!s_side) {
        cudaStreamCreateWithFlags(&s_side, cudaStreamNonBlocking);
        cudaEventCreateWithFlags(&ev_fork, cudaEventDisableTiming);
        cudaEventCreateWithFlags(&ev_join, cudaEventDisableTiming);
    }

    const int chunk = (out_size - 3) / 4;  // 2097152 = 4096*512

    // 0) Convert all fp32 GEMM operands to bf16 hi/lo
    CvtArgs ca;
    ca.src[0] = x;            ca.src[1] = y;
    ca.src[2] = Wq1;          ca.src[3] = Wq2;
    ca.src[4] = (const float*)d_in[4];  ca.src[5] = (const float*)d_in[6];
    ca.src[6] = (const float*)d_in[8];  ca.src[7] = (const float*)d_in[10];
    convert_kernel<<<(CV_TOT / 4 + 255) / 256, 256>>>(ca, cvh, cvl);

    // 1) QKV projections -> bf16 hi/lo
    QkvArgs qa;
    qa.Ah[0] = cvh + CV_X;   qa.Al[0] = cvl + CV_X;
    qa.Bh[0] = cvh + CV_WQ1; qa.Bl[0] = cvl + CV_WQ1;
    qa.Oh[0] = q1h;          qa.Ol[0] = q1l;
    qa.Ah[1] = cvh + CV_Y;   qa.Al[1] = cvl + CV_Y;
    qa.Bh[1] = cvh + CV_WQ2; qa.Bl[1] = cvl + CV_WQ2;
    qa.Oh[1] = q2h;          qa.Ol[1] = q2l;
    hm_gemm_qkv<<<dim3(16, 32, 2), 256, GEMM_SMEM>>>(qa);

    cudaEventRecord(ev_fork, 0);

    // 2) Attention first (default stream) — ortho backfills its tail.
    AttnArgs aa;
    aa.qh[0] = q2h;
    aa.kh[0] = q1h + 512;  aa.kl[0] = q1l + 512;
    aa.vh[0] = q1h + 1024; aa.vl[0] = q1l + 1024;
    aa.oh[0] = preh;                 aa.ol[0] = prel;
    aa.qh[1] = q1h;
    aa.kh[1] = q2h + 512;  aa.kl[1] = q2l + 512;
    aa.vh[1] = q2h + 1024; aa.vl[1] = q2l + 1024;
    aa.oh[1] = preh + 2097152;       aa.ol[1] = prel + 2097152;
    aa.qh[2] = q1h + 1536;
    aa.kh[2] = q1h + 512;  aa.kl[2] = q1l + 512;
    aa.vh[2] = q1h + 1024; aa.vl[2] = q1l + 1024;
    aa.oh[2] = preh + 2 * 2097152;   aa.ol[2] = prel + 2 * 2097152;
    aa.qh[3] = q2h + 1536;
    aa.kh[3] = q2h + 512;  aa.kl[3] = q2l + 512;
    aa.vh[3] = q2h + 1024; aa.vl[3] = q2l + 1024;
    aa.oh[3] = preh + 3 * 2097152;   aa.ol[3] = prel + 3 * 2097152;
    attn_hmma<<<dim3(8, 32, 4), 256, ATTN_SMEM>>>(aa);

    // 3) Ortho on side stream, concurrent with attention.
    cudaStreamWaitEvent(s_side, ev_fork, 0);
    hm_ortho<<<dim3(8, 8, 64), 256, ORTHO_SMEM, s_side>>>(q1h, q1l, q2h, q2l, porth);
    cudaEventRecord(ev_join, s_side);

    // 4) Output projections -> d_out
    ProjArgs pa;
    const int woff[4] = {CV_W0, CV_W0 + 262144, CV_W0 + 524288, CV_W0 + 786432};
    for (int i = 0; i < 4; i++) {
        pa.Ah[i] = preh + (size_t)i * 2097152;
        pa.Al[i] = prel + (size_t)i * 2097152;
        pa.Bh[i] = cvh + woff[i];
        pa.Bl[i] = cvl + woff[i];
        pa.bias[i] = bb[i];
        pa.C[i] = out + (size_t)i * chunk;
    }
    hm_proj<<<dim3(4, 32, 4), 256, GEMM_SMEM>>>(pa);

    // 5) lc on post-projection xc, yc
    lc_kernel<<<4096, 128>>>(out, out + chunk, plc);

    cudaStreamWaitEvent(0, ev_join, 0);

    // 6) scalars: lorthx, lorthy, lc
    finalize_kernel<<<1, 256>>>(porth, plc, out + (size_t)out_size - 3);
}